// round 14
// baseline (speedup 1.0000x reference)
#include <cuda_runtime.h>
#include <cuda_fp16.h>
#include <cstdint>

#define B 32
#define K 1024
#define F 128
#define E 128
#define OUT2 125
#define ALPHA 0.2f

#define CH 64          // j chunk width
#define NCH3 (K / CH)  // 16
#define ABUF 16384     // A-tile: 128 rows x 128 B (swizzled)
#define XBUF 16384     // X-tile: 64 rows x 256 B (swizzled)

// k3g smem offsets (bytes)
#define OFF_S2 0
#define OFF_S1 4096
#define OFF_A 5120                   // 2*ABUF (also W tile 128x256 in phase 2)
#define OFF_X (OFF_A + 2 * ABUF)     // 37888; 2*XBUF (also H tile 128x256)
#define SMEM_K3G (OFF_X + 2 * XBUF)  // 70656

// -------------------- scratch (device globals, allocation-free) ------------
__device__ float g_w1[F];
__device__ float g_w2[F];
__device__ float g_c[2];
__device__ float g_s1[B * K];
__device__ float g_s2[B * K];
__device__ float g_inv[B * K];
__device__ __half g_xh[(size_t)B * K * F];  // fp16 x
__device__ __half g_wh[128 * K];            // fp16 lin2_w (rows 125..127 unused)
__device__ float g_h2[(size_t)B * F * OUT2];

__device__ __forceinline__ uint32_t smem_u32(const void* p) {
    uint32_t a;
    asm("{ .reg .u64 t; cvta.to.shared.u64 t, %1; cvt.u32.u64 %0, t; }" : "=r"(a) : "l"(p));
    return a;
}
__device__ __forceinline__ uint32_t swzA(int row, int c16) {  // pitch 128 B
    return row * 128 + (((c16 ^ row) & 7) << 4);
}
__device__ __forceinline__ uint32_t swzX(int row, int c16) {  // pitch 256 B
    return row * 256 + ((((c16) & 8) | ((c16 ^ row) & 7)) << 4);
}
// FMA-pipe exp: t = v*log2(e); round via magic add; 2^f deg-5 Taylor.
__device__ __forceinline__ float fexp(float v) {
    float t = v * 1.4426950408889634f;
    float tm = t + 12582912.0f;  // 1.5 * 2^23
    int n = __float_as_int(tm) - 0x4B400000;
    float f = t - (tm - 12582912.0f);
    float p = 1.3333558146e-3f;
    p = fmaf(p, f, 9.6181291076e-3f);
    p = fmaf(p, f, 5.5504108664e-2f);
    p = fmaf(p, f, 2.4022650696e-1f);
    p = fmaf(p, f, 6.9314718056e-1f);
    p = fmaf(p, f, 1.0f);
    return __int_as_float(__float_as_int(p) + (n << 23));
}
__device__ __forceinline__ void cp16(uint32_t dst, const void* src) {
    asm volatile("cp.async.cg.shared.global [%0], [%1], 16;" :: "r"(dst), "l"(src) : "memory");
}
__device__ __forceinline__ void cp16z(uint32_t dst, const void* src, int bytes) {
    asm volatile("cp.async.cg.shared.global [%0], [%1], 16, %2;"
                 :: "r"(dst), "l"(src), "r"(bytes) : "memory");
}
__device__ __forceinline__ void cp_commit() {
    asm volatile("cp.async.commit_group;" ::: "memory");
}
#define CP_WAIT(n) asm volatile("cp.async.wait_group %0;" :: "n"(n) : "memory")

__device__ __forceinline__ void ldsm4(uint32_t* r, uint32_t addr) {
    asm volatile("ldmatrix.sync.aligned.m8n8.x4.shared.b16 {%0,%1,%2,%3}, [%4];"
                 : "=r"(r[0]), "=r"(r[1]), "=r"(r[2]), "=r"(r[3]) : "r"(addr));
}
__device__ __forceinline__ void ldsm4t(uint32_t* r, uint32_t addr) {
    asm volatile("ldmatrix.sync.aligned.m8n8.x4.trans.shared.b16 {%0,%1,%2,%3}, [%4];"
                 : "=r"(r[0]), "=r"(r[1]), "=r"(r[2]), "=r"(r[3]) : "r"(addr));
}
#define MMA_F16(acc, a, b0, b1)                                            \
    asm volatile(                                                          \
        "mma.sync.aligned.m16n8k16.row.col.f32.f16.f16.f32 "               \
        "{%0,%1,%2,%3}, {%4,%5,%6,%7}, {%8,%9}, {%0,%1,%2,%3};"            \
        : "+f"((acc)[0]), "+f"((acc)[1]), "+f"((acc)[2]), "+f"((acc)[3])   \
        : "r"((a)[0]), "r"((a)[1]), "r"((a)[2]), "r"((a)[3]),              \
          "r"(b0), "r"(b1))

// ---------------------------------------------------------------------------
// k1: fold a: w1 = lin_w^T a1, c1 = lin_b.a1 (and 2)
// ---------------------------------------------------------------------------
__global__ void k1_prep(const float* __restrict__ lin_w,
                        const float* __restrict__ lin_b,
                        const float* __restrict__ a) {
    int f = threadIdx.x;
    __shared__ float sa1[E], sa2[E], red1[E], red2[E];
    float a1v = a[f], a2v = a[E + f];
    sa1[f] = a1v;
    sa2[f] = a2v;
    __syncthreads();
    float acc1 = 0.f, acc2 = 0.f;
#pragma unroll 8
    for (int e = 0; e < E; e++) {
        float lw = lin_w[e * F + f];
        acc1 += lw * sa1[e];
        acc2 += lw * sa2[e];
    }
    g_w1[f] = acc1;
    g_w2[f] = acc2;
    float lb = lin_b[f];
    red1[f] = lb * a1v;
    red2[f] = lb * a2v;
    __syncthreads();
    for (int s = 64; s > 0; s >>= 1) {
        if (f < s) {
            red1[f] += red1[f + s];
            red2[f] += red2[f + s];
        }
        __syncthreads();
    }
    if (f == 0) {
        g_c[0] = red1[0];
        g_c[1] = red2[0];
    }
}

// ---------------------------------------------------------------------------
// k2: s1/s2 row scores (exact fp32) + fused x -> fp16. One warp per row.
// ---------------------------------------------------------------------------
__global__ void k2_scores(const float* __restrict__ x) {
    int row = (blockIdx.x * blockDim.x + threadIdx.x) >> 5;
    int lane = threadIdx.x & 31;
    if (row >= B * K) return;
    float4 xv = ((const float4*)(x + (size_t)row * F))[lane];
    __half2 hx0 = __floats2half2_rn(xv.x, xv.y);
    __half2 hx1 = __floats2half2_rn(xv.z, xv.w);
    uint2 pk;
    pk.x = *(uint32_t*)&hx0;
    pk.y = *(uint32_t*)&hx1;
    *(uint2*)(g_xh + (size_t)row * F + lane * 4) = pk;

    float4 w1 = ((const float4*)g_w1)[lane];
    float4 w2 = ((const float4*)g_w2)[lane];
    float d1 = xv.x * w1.x + xv.y * w1.y + xv.z * w1.z + xv.w * w1.w;
    float d2 = xv.x * w2.x + xv.y * w2.y + xv.z * w2.z + xv.w * w2.w;
#pragma unroll
    for (int off = 16; off; off >>= 1) {
        d1 += __shfl_xor_sync(~0u, d1, off);
        d2 += __shfl_xor_sync(~0u, d2, off);
    }
    if (lane == 0) {
        g_s1[row] = d1 + g_c[0];
        g_s2[row] = d2 + g_c[1];
    }
}

// ---------------------------------------------------------------------------
// k2h: fp32 -> fp16 conversion (lin2_w only).
// ---------------------------------------------------------------------------
__global__ void k2h_half(const float* __restrict__ src, __half* __restrict__ dst, int n8) {
    int i = blockIdx.x * 256 + threadIdx.x;
    if (i >= n8) return;
    float4 a = ((const float4*)src)[2 * i];
    float4 b = ((const float4*)src)[2 * i + 1];
    __half2 h[4];
    h[0] = __floats2half2_rn(a.x, a.y);
    h[1] = __floats2half2_rn(a.z, a.w);
    h[2] = __floats2half2_rn(b.x, b.y);
    h[3] = __floats2half2_rn(b.z, b.w);
    ((uint4*)dst)[i] = *(uint4*)h;
}

// ---------------------------------------------------------------------------
// k2s: row exp-sums -> g_inv. One warp per row (no attention store).
// ---------------------------------------------------------------------------
__global__ void __launch_bounds__(256) k2s_sums(const float* __restrict__ bias) {
    __shared__ float s2s[K];
    int b = blockIdx.y;
    int tid = threadIdx.x, warp = tid >> 5, lane = tid & 31;
    for (int j = tid; j < K; j += 256) s2s[j] = g_s2[b * K + j];
    __syncthreads();
    int gi = blockIdx.x * 8 + warp;
    float s1 = g_s1[b * K + gi];
    const float4* brow = (const float4*)(bias + (size_t)gi * K);
    const float4* s2s4 = (const float4*)s2s;
    float sum = 0.f;
#pragma unroll
    for (int t = 0; t < 8; t++) {
        int j4 = lane + t * 32;
        float4 bv = brow[j4];
        float4 s2v = s2s4[j4];
        float v;
        v = s1 + s2v.x; v = (v > 0.f ? v : ALPHA * v) + bv.x; sum += fexp(v);
        v = s1 + s2v.y; v = (v > 0.f ? v : ALPHA * v) + bv.y; sum += fexp(v);
        v = s1 + s2v.z; v = (v > 0.f ? v : ALPHA * v) + bv.z; sum += fexp(v);
        v = s1 + s2v.w; v = (v > 0.f ? v : ALPHA * v) + bv.w; sum += fexp(v);
    }
#pragma unroll
    for (int off = 16; off; off >>= 1) sum += __shfl_xor_sync(~0u, sum, off);
    if (lane == 0) g_inv[b * K + gi] = 1.0f / sum;
}

// ---------------------------------------------------------------------------
// k3g: fused [softmax GEMM + inline attn store] + [lin2 GEMM], swizzled smem.
// 512 threads = 16 warps as 4(m) x 4(n); warp tile 32 x 32; 2 blocks/SM.
// inv is precomputed (k2s): A-tile holds normalized P; attn written inline.
// ---------------------------------------------------------------------------
__global__ void __launch_bounds__(512, 2) k3g(const float* __restrict__ x,
                                              const float* __restrict__ bias,
                                              float* __restrict__ attn) {
    extern __shared__ char sm[];
    const uint32_t sbase = smem_u32(sm);
    float* s2s = (float*)(sm + OFF_S2);
    float* s1s = (float*)(sm + OFF_S1);

    const int tid = threadIdx.x;
    const int wid = tid >> 5, lane = tid & 31;
    const int b = blockIdx.y;
    const int i0 = blockIdx.x * 128;
    const int warp_m = (wid >> 2) * 32;  // 0,32,64,96
    const int warp_n = (wid & 3) * 32;   // 0..96
    const int wn8 = warp_n >> 3;
    const int qr = lane >> 2, qc = lane & 3;
    const int lrow = (lane & 7) | (((lane >> 3) & 1) << 3);
    const int hi = lane >> 4;  // 0 or 1
    const int r7 = lane & 7;

    const float* Xb = x + (size_t)b * K * F;
    const __half* Xh = g_xh + (size_t)b * K * F;

    const int prow = tid >> 2;            // 0..127 (E row)
    const int pj0 = (tid & 3) * 16;       // j base within chunk
    const int pc16 = (tid & 3) * 2;       // 16B-col base
    const int jx = tid >> 3, cx = tid & 7;  // X staging coords

    for (int j = tid; j < K; j += 512) s2s[j] = g_s2[b * K + j];
    if (tid < 128) s1s[tid] = g_s1[b * K + i0 + tid];
    __syncthreads();

    const float s1 = s1s[prow];
    const float iv = g_inv[b * K + i0 + prow];

    float acc[2][4][4];
#pragma unroll
    for (int mt = 0; mt < 2; mt++)
#pragma unroll
        for (int nt = 0; nt < 4; nt++)
#pragma unroll
            for (int q = 0; q < 4; q++) acc[mt][nt][q] = 0.f;

#define STAGE_X(c, bi)                                                          \
    do {                                                                        \
        uint32_t xd = sbase + OFF_X + (bi) * XBUF;                              \
        _Pragma("unroll") for (int t = 0; t < 2; t++) {                         \
            int c16 = cx * 2 + t;                                               \
            cp16(xd + swzX(jx, c16),                                            \
                 Xh + (size_t)((c) * CH + jx) * F + c16 * 8);                   \
        }                                                                       \
        cp_commit();                                                            \
    } while (0)

#define COMPUTE_E(c, bi)                                                             \
    do {                                                                             \
        const float* brow = bias + (size_t)(i0 + prow) * K + (c) * CH + pj0;         \
        const float* s2p = s2s + (c) * CH + pj0;                                     \
        float* arow = attn + ((size_t)(b * K + i0 + prow)) * K + (c) * CH + pj0;     \
        char* abase = sm + OFF_A + (bi) * ABUF;                                      \
        _Pragma("unroll") for (int t = 0; t < 2; t++) {                              \
            uint32_t hb[4];                                                          \
            _Pragma("unroll") for (int qq = 0; qq < 2; qq++) {                       \
                int q = t * 2 + qq;                                                  \
                float4 bv = *(const float4*)(brow + q * 4);                          \
                float4 s2v = *(const float4*)(s2p + q * 4);                          \
                float v;                                                             \
                float4 e;                                                            \
                v = s1 + s2v.x; v = (v > 0.f ? v : ALPHA * v) + bv.x;                \
                e.x = fexp(v) * iv;                                                  \
                v = s1 + s2v.y; v = (v > 0.f ? v : ALPHA * v) + bv.y;                \
                e.y = fexp(v) * iv;                                                  \
                v = s1 + s2v.z; v = (v > 0.f ? v : ALPHA * v) + bv.z;                \
                e.z = fexp(v) * iv;                                                  \
                v = s1 + s2v.w; v = (v > 0.f ? v : ALPHA * v) + bv.w;                \
                e.w = fexp(v) * iv;                                                  \
                *(float4*)(arow + q * 4) = e;                                        \
                __half2 p0 = __floats2half2_rn(e.x, e.y);                            \
                __half2 p1 = __floats2half2_rn(e.z, e.w);                            \
                hb[qq * 2] = *(uint32_t*)&p0;                                        \
                hb[qq * 2 + 1] = *(uint32_t*)&p1;                                    \
            }                                                                        \
            *(uint4*)(abase + swzA(prow, pc16 + t)) = *(uint4*)hb;                   \
        }                                                                            \
    } while (0)

    STAGE_X(0, 0);
    COMPUTE_E(0, 0);
    for (int c = 0; c < NCH3; c++) {
        int bi = c & 1;
        if (c + 1 < NCH3) {
            STAGE_X(c + 1, bi ^ 1);
            COMPUTE_E(c + 1, bi ^ 1);
            CP_WAIT(1);
        } else {
            CP_WAIT(0);
        }
        __syncthreads();
        uint32_t aA = sbase + OFF_A + bi * ABUF;
        uint32_t aX = sbase + OFF_X + bi * XBUF;
#pragma unroll
        for (int kk = 0; kk < 4; kk++) {
            int sA = ((kk * 2 + hi) ^ r7) & 7;
            uint32_t af[2][4];
#pragma unroll
            for (int mt = 0; mt < 2; mt++)
                ldsm4(af[mt], aA + (warp_m + mt * 16 + lrow) * 128 + (sA << 4));
            uint32_t bf[2][4];
#pragma unroll
            for (int ntp = 0; ntp < 2; ntp++) {
                int c16 = wn8 + 2 * ntp + hi;
                ldsm4t(bf[ntp], aX + swzX(kk * 16 + lrow, c16));
            }
#pragma unroll
            for (int mt = 0; mt < 2; mt++) {
                MMA_F16(acc[mt][0], af[mt], bf[0][0], bf[0][1]);
                MMA_F16(acc[mt][1], af[mt], bf[0][2], bf[0][3]);
                MMA_F16(acc[mt][2], af[mt], bf[1][0], bf[1][1]);
                MMA_F16(acc[mt][3], af[mt], bf[1][2], bf[1][3]);
            }
        }
        __syncthreads();
    }

    // ---- epilogue: h = acc + x -> fp16 H-tile (OFF_X, pitch 256 swz) ----
#pragma unroll
    for (int mt = 0; mt < 2; mt++) {
        int lr = warp_m + mt * 16 + qr;
        int r0 = i0 + lr;
#pragma unroll
        for (int nt = 0; nt < 4; nt++) {
            int fc = warp_n + nt * 8 + qc * 2;
            int c16 = wn8 + nt;
            float2 xv0 = *(const float2*)(Xb + (size_t)r0 * F + fc);
            float2 xv1 = *(const float2*)(Xb + (size_t)(r0 + 8) * F + fc);
            *(__half2*)(sm + OFF_X + swzX(lr, c16) + 4 * qc) =
                __floats2half2_rn(acc[mt][nt][0] + xv0.x, acc[mt][nt][1] + xv0.y);
            *(__half2*)(sm + OFF_X + swzX(lr + 8, c16) + 4 * qc) =
                __floats2half2_rn(acc[mt][nt][2] + xv1.x, acc[mt][nt][3] + xv1.y);
        }
    }

    // ---- stage W k-slice [128 o x 128 k] into OFF_A (pitch 256 swz) ----
    {
        int wrow = tid >> 2;
        int wc0 = (tid & 3) * 4;
        int vb = wrow < OUT2 ? 16 : 0;
        const __half* wsrc = g_wh + (size_t)(wrow < OUT2 ? wrow : 0) * K + i0;
#pragma unroll
        for (int t = 0; t < 4; t++) {
            int c16 = wc0 + t;
            cp16z(sbase + OFF_A + swzX(wrow, c16), wsrc + c16 * 8, vb);
        }
        cp_commit();
    }
    CP_WAIT(0);
    __syncthreads();

    // ---- phase 2: D[o][f] = W @ H  (M=128 o, N=128 f, K=128) ----
#pragma unroll
    for (int mt = 0; mt < 2; mt++)
#pragma unroll
        for (int nt = 0; nt < 4; nt++)
#pragma unroll
            for (int q = 0; q < 4; q++) acc[mt][nt][q] = 0.f;

#pragma unroll
    for (int kk = 0; kk < 8; kk++) {
        uint32_t af[2][4];
#pragma unroll
        for (int mt = 0; mt < 2; mt++)
            ldsm4(af[mt], sbase + OFF_A + swzX(warp_m + mt * 16 + lrow, kk * 2 + hi));
        uint32_t bf[2][4];
#pragma unroll
        for (int ntp = 0; ntp < 2; ntp++)
            ldsm4t(bf[ntp], sbase + OFF_X + swzX(kk * 16 + lrow, wn8 + 2 * ntp + hi));
#pragma unroll
        for (int mt = 0; mt < 2; mt++) {
            MMA_F16(acc[mt][0], af[mt], bf[0][0], bf[0][1]);
            MMA_F16(acc[mt][1], af[mt], bf[0][2], bf[0][3]);
            MMA_F16(acc[mt][2], af[mt], bf[1][0], bf[1][1]);
            MMA_F16(acc[mt][3], af[mt], bf[1][2], bf[1][3]);
        }
    }

    // ---- atomic accumulate into g_h2[b][f][o] ----
    float* h2b = g_h2 + (size_t)b * F * OUT2;
#pragma unroll
    for (int mt = 0; mt < 2; mt++) {
        int o0 = warp_m + mt * 16 + qr;
#pragma unroll
        for (int nt = 0; nt < 4; nt++) {
            int fc = warp_n + nt * 8 + qc * 2;
            if (o0 < OUT2) {
                atomicAdd(&h2b[(size_t)fc * OUT2 + o0], acc[mt][nt][0]);
                atomicAdd(&h2b[(size_t)(fc + 1) * OUT2 + o0], acc[mt][nt][1]);
            }
            if (o0 + 8 < OUT2) {
                atomicAdd(&h2b[(size_t)fc * OUT2 + o0 + 8], acc[mt][nt][2]);
                atomicAdd(&h2b[(size_t)(fc + 1) * OUT2 + o0 + 8], acc[mt][nt][3]);
            }
        }
    }
}

// ---------------------------------------------------------------------------
// k5: out = relu(g_h2 + lin2_b)
// ---------------------------------------------------------------------------
__global__ void k5_out(const float* __restrict__ lin2_b, float* __restrict__ out) {
    int i = blockIdx.x * 256 + threadIdx.x;
    if (i >= B * F * OUT2) return;
    float v = g_h2[i] + lin2_b[i % OUT2];
    out[i] = v > 0.f ? v : 0.f;
}

// ---------------------------------------------------------------------------
extern "C" void kernel_launch(void* const* d_in, const int* in_sizes, int n_in,
                              void* d_out, int out_size) {
    const float* x      = (const float*)d_in[0];
    const float* lin_w  = (const float*)d_in[1];
    const float* lin_b  = (const float*)d_in[2];
    const float* a      = (const float*)d_in[3];
    const float* bias   = (const float*)d_in[4];
    const float* lin2_w = (const float*)d_in[5];
    const float* lin2_b = (const float*)d_in[6];
    float* out = (float*)d_out;
    float* out_h2 = out;                           // (B,F,OUT2)
    float* out_attn = out + (size_t)B * F * OUT2;  // (B,K,K)

    cudaFuncSetAttribute(k3g, cudaFuncAttributeMaxDynamicSharedMemorySize, SMEM_K3G);

    void* wh = nullptr;
    void* h2 = nullptr;
    cudaGetSymbolAddress(&wh, g_wh);
    cudaGetSymbolAddress(&h2, g_h2);

    cudaMemsetAsync(h2, 0, sizeof(float) * B * F * OUT2);
    k1_prep<<<1, 128>>>(lin_w, lin_b, a);
    k2_scores<<<(B * K) / 8, 256>>>(x);
    k2h_half<<<(OUT2 * K / 8 + 255) / 256, 256>>>(lin2_w, (__half*)wh, OUT2 * K / 8);
    k2s_sums<<<dim3(K / 8, B), 256>>>(bias);
    k3g<<<dim3(K / 128, B), 512, SMEM_K3G>>>(x, bias, out_attn);
    k5_out<<<(B * F * OUT2 + 255) / 256, 256>>>(lin2_b, out_h2);
}

// round 15
// speedup vs baseline: 1.2576x; 1.2576x over previous
#include <cuda_runtime.h>
#include <cuda_fp16.h>
#include <cstdint>

#define B 32
#define K 1024
#define F 128
#define E 128
#define OUT2 125
#define ALPHA 0.2f

#define CH 64          // j chunk width
#define NCH3 (K / CH)  // 16
#define ABUF 16384     // A-tile: 128 rows x 128 B (swizzled)
#define XBUF 16384     // X-tile: 64 rows x 256 B (swizzled)
#define BBUF 16384     // bias tile: 128 rows x 128 B (fp16, linear)

// k3g smem offsets (bytes)
#define OFF_S2 0
#define OFF_S1 4096
#define OFF_INV 4608
#define OFF_A 5120                   // 2*ABUF (also W tile 128x256 in phase 2)
#define OFF_X (OFF_A + 2 * ABUF)     // 37888; 2*XBUF (also H tile 128x256)
#define OFF_B (OFF_X + 2 * XBUF)     // 70656; 2*BBUF
#define SMEM_K3G (OFF_B + 2 * BBUF)  // 103424

// -------------------- scratch (device globals, allocation-free) ------------
__device__ float g_w1[F];
__device__ float g_w2[F];
__device__ float g_c[2];
__device__ float g_s1[B * K];
__device__ float g_s2[B * K];
__device__ float g_inv[B * K];
__device__ __half g_xh[(size_t)B * K * F];  // fp16 x
__device__ __half g_wh[128 * K];            // fp16 lin2_w (rows 125..127 unused)
__device__ __half g_bh[K * K];              // fp16 bias (2 MB)
__device__ float g_h2[(size_t)B * F * OUT2];

__device__ __forceinline__ uint32_t smem_u32(const void* p) {
    uint32_t a;
    asm("{ .reg .u64 t; cvta.to.shared.u64 t, %1; cvt.u32.u64 %0, t; }" : "=r"(a) : "l"(p));
    return a;
}
__device__ __forceinline__ uint32_t swzA(int row, int c16) {  // pitch 128 B
    return row * 128 + (((c16 ^ row) & 7) << 4);
}
__device__ __forceinline__ uint32_t swzX(int row, int c16) {  // pitch 256 B
    return row * 256 + ((((c16) & 8) | ((c16 ^ row) & 7)) << 4);
}
// FMA-pipe exp: t = v*log2(e); round via magic add; 2^f deg-5 Taylor.
__device__ __forceinline__ float fexp(float v) {
    float t = v * 1.4426950408889634f;
    float tm = t + 12582912.0f;  // 1.5 * 2^23
    int n = __float_as_int(tm) - 0x4B400000;
    float f = t - (tm - 12582912.0f);
    float p = 1.3333558146e-3f;
    p = fmaf(p, f, 9.6181291076e-3f);
    p = fmaf(p, f, 5.5504108664e-2f);
    p = fmaf(p, f, 2.4022650696e-1f);
    p = fmaf(p, f, 6.9314718056e-1f);
    p = fmaf(p, f, 1.0f);
    return __int_as_float(__float_as_int(p) + (n << 23));
}
__device__ __forceinline__ void cp16(uint32_t dst, const void* src) {
    asm volatile("cp.async.cg.shared.global [%0], [%1], 16;" :: "r"(dst), "l"(src) : "memory");
}
__device__ __forceinline__ void cp16z(uint32_t dst, const void* src, int bytes) {
    asm volatile("cp.async.cg.shared.global [%0], [%1], 16, %2;"
                 :: "r"(dst), "l"(src), "r"(bytes) : "memory");
}
__device__ __forceinline__ void cp_commit() {
    asm volatile("cp.async.commit_group;" ::: "memory");
}
#define CP_WAIT(n) asm volatile("cp.async.wait_group %0;" :: "n"(n) : "memory")

__device__ __forceinline__ void ldsm4(uint32_t* r, uint32_t addr) {
    asm volatile("ldmatrix.sync.aligned.m8n8.x4.shared.b16 {%0,%1,%2,%3}, [%4];"
                 : "=r"(r[0]), "=r"(r[1]), "=r"(r[2]), "=r"(r[3]) : "r"(addr));
}
__device__ __forceinline__ void ldsm4t(uint32_t* r, uint32_t addr) {
    asm volatile("ldmatrix.sync.aligned.m8n8.x4.trans.shared.b16 {%0,%1,%2,%3}, [%4];"
                 : "=r"(r[0]), "=r"(r[1]), "=r"(r[2]), "=r"(r[3]) : "r"(addr));
}
#define MMA_F16(acc, a, b0, b1)                                            \
    asm volatile(                                                          \
        "mma.sync.aligned.m16n8k16.row.col.f32.f16.f16.f32 "               \
        "{%0,%1,%2,%3}, {%4,%5,%6,%7}, {%8,%9}, {%0,%1,%2,%3};"            \
        : "+f"((acc)[0]), "+f"((acc)[1]), "+f"((acc)[2]), "+f"((acc)[3])   \
        : "r"((a)[0]), "r"((a)[1]), "r"((a)[2]), "r"((a)[3]),              \
          "r"(b0), "r"(b1))

// ---------------------------------------------------------------------------
// k1: fold a: w1 = lin_w^T a1, c1 = lin_b.a1 (and 2)
// ---------------------------------------------------------------------------
__global__ void k1_prep(const float* __restrict__ lin_w,
                        const float* __restrict__ lin_b,
                        const float* __restrict__ a) {
    int f = threadIdx.x;
    __shared__ float sa1[E], sa2[E], red1[E], red2[E];
    float a1v = a[f], a2v = a[E + f];
    sa1[f] = a1v;
    sa2[f] = a2v;
    __syncthreads();
    float acc1 = 0.f, acc2 = 0.f;
#pragma unroll 8
    for (int e = 0; e < E; e++) {
        float lw = lin_w[e * F + f];
        acc1 += lw * sa1[e];
        acc2 += lw * sa2[e];
    }
    g_w1[f] = acc1;
    g_w2[f] = acc2;
    float lb = lin_b[f];
    red1[f] = lb * a1v;
    red2[f] = lb * a2v;
    __syncthreads();
    for (int s = 64; s > 0; s >>= 1) {
        if (f < s) {
            red1[f] += red1[f + s];
            red2[f] += red2[f + s];
        }
        __syncthreads();
    }
    if (f == 0) {
        g_c[0] = red1[0];
        g_c[1] = red2[0];
    }
}

// ---------------------------------------------------------------------------
// k2: s1/s2 row scores (exact fp32) + fused x -> fp16. One warp per row.
// ---------------------------------------------------------------------------
__global__ void k2_scores(const float* __restrict__ x) {
    int row = (blockIdx.x * blockDim.x + threadIdx.x) >> 5;
    int lane = threadIdx.x & 31;
    if (row >= B * K) return;
    float4 xv = ((const float4*)(x + (size_t)row * F))[lane];
    __half2 hx0 = __floats2half2_rn(xv.x, xv.y);
    __half2 hx1 = __floats2half2_rn(xv.z, xv.w);
    uint2 pk;
    pk.x = *(uint32_t*)&hx0;
    pk.y = *(uint32_t*)&hx1;
    *(uint2*)(g_xh + (size_t)row * F + lane * 4) = pk;

    float4 w1 = ((const float4*)g_w1)[lane];
    float4 w2 = ((const float4*)g_w2)[lane];
    float d1 = xv.x * w1.x + xv.y * w1.y + xv.z * w1.z + xv.w * w1.w;
    float d2 = xv.x * w2.x + xv.y * w2.y + xv.z * w2.z + xv.w * w2.w;
#pragma unroll
    for (int off = 16; off; off >>= 1) {
        d1 += __shfl_xor_sync(~0u, d1, off);
        d2 += __shfl_xor_sync(~0u, d2, off);
    }
    if (lane == 0) {
        g_s1[row] = d1 + g_c[0];
        g_s2[row] = d2 + g_c[1];
    }
}

// ---------------------------------------------------------------------------
// k2h: fp32 -> fp16 conversion (lin2_w and bias).
// ---------------------------------------------------------------------------
__global__ void k2h_half(const float* __restrict__ src, __half* __restrict__ dst, int n8) {
    int i = blockIdx.x * 256 + threadIdx.x;
    if (i >= n8) return;
    float4 a = ((const float4*)src)[2 * i];
    float4 b = ((const float4*)src)[2 * i + 1];
    __half2 h[4];
    h[0] = __floats2half2_rn(a.x, a.y);
    h[1] = __floats2half2_rn(a.z, a.w);
    h[2] = __floats2half2_rn(b.x, b.y);
    h[3] = __floats2half2_rn(b.z, b.w);
    ((uint4*)dst)[i] = *(uint4*)h;
}

// ---------------------------------------------------------------------------
// k3g: fused [softmax-numerator GEMM] + [lin2 GEMM], fully cp.async-fed.
// 512 threads = 16 warps as 4(m) x 4(n); warp tile 32 x 32; 2 blocks/SM.
// Per chunk: stage X+bias(c+1); wait(c); E(c) from smem (no gmem); MMA(c).
// ---------------------------------------------------------------------------
__global__ void __launch_bounds__(512, 2) k3g(const float* __restrict__ x) {
    extern __shared__ char sm[];
    const uint32_t sbase = smem_u32(sm);
    float* s2s = (float*)(sm + OFF_S2);
    float* s1s = (float*)(sm + OFF_S1);
    float* invs = (float*)(sm + OFF_INV);

    const int tid = threadIdx.x;
    const int wid = tid >> 5, lane = tid & 31;
    const int b = blockIdx.y;
    const int i0 = blockIdx.x * 128;
    const int warp_m = (wid >> 2) * 32;  // 0,32,64,96
    const int warp_n = (wid & 3) * 32;   // 0..96
    const int wn8 = warp_n >> 3;
    const int qr = lane >> 2, qc = lane & 3;
    const int lrow = (lane & 7) | (((lane >> 3) & 1) << 3);
    const int hi = lane >> 4;  // 0 or 1
    const int r7 = lane & 7;

    const float* Xb = x + (size_t)b * K * F;
    const __half* Xh = g_xh + (size_t)b * K * F;

    const int prow = tid >> 2;            // 0..127 (E row)
    const int pj0 = (tid & 3) * 16;       // j base within chunk
    const int pc16 = (tid & 3) * 2;       // A-tile 16B-col base
    const int jx = tid >> 3, cx = tid & 7;  // X staging coords

    for (int j = tid; j < K; j += 512) s2s[j] = g_s2[b * K + j];
    if (tid < 128) s1s[tid] = g_s1[b * K + i0 + tid];
    __syncthreads();

    const float s1 = s1s[prow];
    float rsum = 0.f;

    float acc[2][4][4];
#pragma unroll
    for (int mt = 0; mt < 2; mt++)
#pragma unroll
        for (int nt = 0; nt < 4; nt++)
#pragma unroll
            for (int q = 0; q < 4; q++) acc[mt][nt][q] = 0.f;

    // one commit group = X tile + bias tile for chunk c
#define STAGE_XB(c, bi)                                                         \
    do {                                                                        \
        uint32_t xd = sbase + OFF_X + (bi) * XBUF;                              \
        _Pragma("unroll") for (int t = 0; t < 2; t++) {                         \
            int c16 = cx * 2 + t;                                               \
            cp16(xd + swzX(jx, c16),                                            \
                 Xh + (size_t)((c) * CH + jx) * F + c16 * 8);                   \
        }                                                                       \
        uint32_t bd = sbase + OFF_B + (bi) * BBUF;                              \
        _Pragma("unroll") for (int t = 0; t < 2; t++) {                         \
            int c16 = (tid & 3) * 2 + t;                                        \
            cp16(bd + prow * 128 + c16 * 16,                                    \
                 g_bh + (size_t)(i0 + prow) * K + (c) * CH + c16 * 8);          \
        }                                                                       \
        cp_commit();                                                            \
    } while (0)

    // E(c): bias + s2 from smem only; fexp; fp16 A-tile + row sum
#define COMPUTE_E(c, bi)                                                             \
    do {                                                                             \
        const __half* bsm = (const __half*)(sm + OFF_B + (bi) * BBUF + prow * 128) + pj0; \
        const float* s2p = s2s + (c) * CH + pj0;                                     \
        char* abase = sm + OFF_A + (bi) * ABUF;                                      \
        _Pragma("unroll") for (int t = 0; t < 2; t++) {                              \
            uint4 braw = *(const uint4*)(bsm + t * 8);                               \
            const __half2* bh2 = (const __half2*)&braw;                              \
            uint32_t hb[4];                                                          \
            _Pragma("unroll") for (int qq = 0; qq < 2; qq++) {                       \
                float2 b01 = __half22float2(bh2[qq * 2]);                            \
                float2 b23 = __half22float2(bh2[qq * 2 + 1]);                        \
                float4 s2v = *(const float4*)(s2p + t * 8 + qq * 4);                 \
                float v, e0, e1, e2, e3;                                             \
                v = s1 + s2v.x; v = (v > 0.f ? v : ALPHA * v) + b01.x; e0 = fexp(v); \
                v = s1 + s2v.y; v = (v > 0.f ? v : ALPHA * v) + b01.y; e1 = fexp(v); \
                v = s1 + s2v.z; v = (v > 0.f ? v : ALPHA * v) + b23.x; e2 = fexp(v); \
                v = s1 + s2v.w; v = (v > 0.f ? v : ALPHA * v) + b23.y; e3 = fexp(v); \
                rsum += (e0 + e1) + (e2 + e3);                                       \
                __half2 p0 = __floats2half2_rn(e0, e1);                              \
                __half2 p1 = __floats2half2_rn(e2, e3);                              \
                hb[qq * 2] = *(uint32_t*)&p0;                                        \
                hb[qq * 2 + 1] = *(uint32_t*)&p1;                                    \
            }                                                                        \
            *(uint4*)(abase + swzA(prow, pc16 + t)) = *(uint4*)hb;                   \
        }                                                                            \
    } while (0)

    STAGE_XB(0, 0);
    for (int c = 0; c < NCH3; c++) {
        int bi = c & 1;
        if (c + 1 < NCH3) {
            STAGE_XB(c + 1, bi ^ 1);
            CP_WAIT(1);
        } else {
            CP_WAIT(0);
        }
        __syncthreads();  // chunk-c tiles visible to all
        COMPUTE_E(c, bi);
        __syncthreads();  // A-tile complete
        uint32_t aA = sbase + OFF_A + bi * ABUF;
        uint32_t aX = sbase + OFF_X + bi * XBUF;
#pragma unroll
        for (int kk = 0; kk < 4; kk++) {
            int sA = ((kk * 2 + hi) ^ r7) & 7;
            uint32_t af[2][4];
#pragma unroll
            for (int mt = 0; mt < 2; mt++)
                ldsm4(af[mt], aA + (warp_m + mt * 16 + lrow) * 128 + (sA << 4));
            uint32_t bf[2][4];
#pragma unroll
            for (int ntp = 0; ntp < 2; ntp++) {
                int c16 = wn8 + 2 * ntp + hi;
                ldsm4t(bf[ntp], aX + swzX(kk * 16 + lrow, c16));
            }
#pragma unroll
            for (int mt = 0; mt < 2; mt++) {
                MMA_F16(acc[mt][0], af[mt], bf[0][0], bf[0][1]);
                MMA_F16(acc[mt][1], af[mt], bf[0][2], bf[0][3]);
                MMA_F16(acc[mt][2], af[mt], bf[1][0], bf[1][1]);
                MMA_F16(acc[mt][3], af[mt], bf[1][2], bf[1][3]);
            }
        }
        __syncthreads();  // MMA done before next stage overwrites buffers
    }

    // ---- inv: 4 threads share a row ----
    float total = rsum + __shfl_xor_sync(~0u, rsum, 1);
    total += __shfl_xor_sync(~0u, total, 2);
    if ((tid & 3) == 0) {
        float iv = 1.0f / total;
        invs[prow] = iv;
        g_inv[b * K + i0 + prow] = iv;
    }
    __syncthreads();

    // ---- epilogue: h = acc*inv + x -> fp16 H-tile (OFF_X, pitch 256 swz) ----
#pragma unroll
    for (int mt = 0; mt < 2; mt++) {
        int lr = warp_m + mt * 16 + qr;
        float ivA = invs[lr];
        float ivB = invs[lr + 8];
        int r0 = i0 + lr;
#pragma unroll
        for (int nt = 0; nt < 4; nt++) {
            int fc = warp_n + nt * 8 + qc * 2;
            int c16 = wn8 + nt;
            float2 xv0 = *(const float2*)(Xb + (size_t)r0 * F + fc);
            float2 xv1 = *(const float2*)(Xb + (size_t)(r0 + 8) * F + fc);
            *(__half2*)(sm + OFF_X + swzX(lr, c16) + 4 * qc) =
                __floats2half2_rn(acc[mt][nt][0] * ivA + xv0.x, acc[mt][nt][1] * ivA + xv0.y);
            *(__half2*)(sm + OFF_X + swzX(lr + 8, c16) + 4 * qc) =
                __floats2half2_rn(acc[mt][nt][2] * ivB + xv1.x, acc[mt][nt][3] * ivB + xv1.y);
        }
    }

    // ---- stage W k-slice [128 o x 128 k] into OFF_A (pitch 256 swz) ----
    {
        int wrow = tid >> 2;
        int wc0 = (tid & 3) * 4;
        int vb = wrow < OUT2 ? 16 : 0;
        const __half* wsrc = g_wh + (size_t)(wrow < OUT2 ? wrow : 0) * K + i0;
#pragma unroll
        for (int t = 0; t < 4; t++) {
            int c16 = wc0 + t;
            cp16z(sbase + OFF_A + swzX(wrow, c16), wsrc + c16 * 8, vb);
        }
        cp_commit();
    }
    CP_WAIT(0);
    __syncthreads();

    // ---- phase 2: D[o][f] = W @ H  (M=128 o, N=128 f, K=128) ----
#pragma unroll
    for (int mt = 0; mt < 2; mt++)
#pragma unroll
        for (int nt = 0; nt < 4; nt++)
#pragma unroll
            for (int q = 0; q < 4; q++) acc[mt][nt][q] = 0.f;

#pragma unroll
    for (int kk = 0; kk < 8; kk++) {
        uint32_t af[2][4];
#pragma unroll
        for (int mt = 0; mt < 2; mt++)
            ldsm4(af[mt], sbase + OFF_A + swzX(warp_m + mt * 16 + lrow, kk * 2 + hi));
        uint32_t bf[2][4];
#pragma unroll
        for (int ntp = 0; ntp < 2; ntp++)
            ldsm4t(bf[ntp], sbase + OFF_X + swzX(kk * 16 + lrow, wn8 + 2 * ntp + hi));
#pragma unroll
        for (int mt = 0; mt < 2; mt++) {
            MMA_F16(acc[mt][0], af[mt], bf[0][0], bf[0][1]);
            MMA_F16(acc[mt][1], af[mt], bf[0][2], bf[0][3]);
            MMA_F16(acc[mt][2], af[mt], bf[1][0], bf[1][1]);
            MMA_F16(acc[mt][3], af[mt], bf[1][2], bf[1][3]);
        }
    }

    // ---- atomic accumulate into g_h2[b][f][o] ----
    float* h2b = g_h2 + (size_t)b * F * OUT2;
#pragma unroll
    for (int mt = 0; mt < 2; mt++) {
        int o0 = warp_m + mt * 16 + qr;
#pragma unroll
        for (int nt = 0; nt < 4; nt++) {
            int fc = warp_n + nt * 8 + qc * 2;
            if (o0 < OUT2) {
                atomicAdd(&h2b[(size_t)fc * OUT2 + o0], acc[mt][nt][0]);
                atomicAdd(&h2b[(size_t)(fc + 1) * OUT2 + o0], acc[mt][nt][1]);
            }
            if (o0 + 8 < OUT2) {
                atomicAdd(&h2b[(size_t)fc * OUT2 + o0 + 8], acc[mt][nt][2]);
                atomicAdd(&h2b[(size_t)(fc + 1) * OUT2 + o0 + 8], acc[mt][nt][3]);
            }
        }
    }
}

// ---------------------------------------------------------------------------
// k3w: stream attention = fexp(leaky(s1+s2)+bias_fp32) * inv. Pure bandwidth.
// ---------------------------------------------------------------------------
__global__ void __launch_bounds__(256) k3w(const float* __restrict__ bias,
                                           float* __restrict__ attn) {
    __shared__ float s2s[K];
    int b = blockIdx.y;
    int tid = threadIdx.x, warp = tid >> 5, lane = tid & 31;
    for (int j = tid; j < K; j += 256) s2s[j] = g_s2[b * K + j];
    __syncthreads();
    int gi = blockIdx.x * 8 + warp;
    float s1 = g_s1[b * K + gi];
    float iv = g_inv[b * K + gi];
    const float4* brow = (const float4*)(bias + (size_t)gi * K);
    const float4* s2s4 = (const float4*)s2s;
    float4* arow = (float4*)(attn + ((size_t)(b * K + gi)) * K);
#pragma unroll
    for (int t = 0; t < 8; t++) {
        int j4 = lane + t * 32;
        float4 bv = brow[j4];
        float4 s2v = s2s4[j4];
        float v;
        float4 p;
        v = s1 + s2v.x; v = (v > 0.f ? v : ALPHA * v) + bv.x; p.x = fexp(v) * iv;
        v = s1 + s2v.y; v = (v > 0.f ? v : ALPHA * v) + bv.y; p.y = fexp(v) * iv;
        v = s1 + s2v.z; v = (v > 0.f ? v : ALPHA * v) + bv.z; p.z = fexp(v) * iv;
        v = s1 + s2v.w; v = (v > 0.f ? v : ALPHA * v) + bv.w; p.w = fexp(v) * iv;
        arow[j4] = p;
    }
}

// ---------------------------------------------------------------------------
// k5: out = relu(g_h2 + lin2_b)
// ---------------------------------------------------------------------------
__global__ void k5_out(const float* __restrict__ lin2_b, float* __restrict__ out) {
    int i = blockIdx.x * 256 + threadIdx.x;
    if (i >= B * F * OUT2) return;
    float v = g_h2[i] + lin2_b[i % OUT2];
    out[i] = v > 0.f ? v : 0.f;
}

// ---------------------------------------------------------------------------
extern "C" void kernel_launch(void* const* d_in, const int* in_sizes, int n_in,
                              void* d_out, int out_size) {
    const float* x      = (const float*)d_in[0];
    const float* lin_w  = (const float*)d_in[1];
    const float* lin_b  = (const float*)d_in[2];
    const float* a      = (const float*)d_in[3];
    const float* bias   = (const float*)d_in[4];
    const float* lin2_w = (const float*)d_in[5];
    const float* lin2_b = (const float*)d_in[6];
    float* out = (float*)d_out;
    float* out_h2 = out;                           // (B,F,OUT2)
    float* out_attn = out + (size_t)B * F * OUT2;  // (B,K,K)

    cudaFuncSetAttribute(k3g, cudaFuncAttributeMaxDynamicSharedMemorySize, SMEM_K3G);

    void* wh = nullptr;
    void* bh = nullptr;
    void* h2 = nullptr;
    cudaGetSymbolAddress(&wh, g_wh);
    cudaGetSymbolAddress(&bh, g_bh);
    cudaGetSymbolAddress(&h2, g_h2);

    cudaMemsetAsync(h2, 0, sizeof(float) * B * F * OUT2);
    k1_prep<<<1, 128>>>(lin_w, lin_b, a);
    k2_scores<<<(B * K) / 8, 256>>>(x);
    k2h_half<<<(OUT2 * K / 8 + 255) / 256, 256>>>(lin2_w, (__half*)wh, OUT2 * K / 8);
    k2h_half<<<(K * K / 8 + 255) / 256, 256>>>(bias, (__half*)bh, K * K / 8);
    k3g<<<dim3(K / 128, B), 512, SMEM_K3G>>>(x);
    k3w<<<dim3(K / 8, B), 256>>>(bias, out_attn);
    k5_out<<<(B * F * OUT2 + 255) / 256, 256>>>(lin2_b, out_h2);
}